// round 16
// baseline (speedup 1.0000x reference)
#include <cuda_runtime.h>
#include <cuda_bf16.h>
#include <cuda_fp16.h>
#include <cstdint>

// Problem dims
#define DB 32
#define DT 64
#define DV 50257
#define DVP 50304   // padded vocab (393 * 128)
#define DE 256
#define DH 512
#define G4H 2048   // 4*H
#define H2  1024   // 2*H
#define NROWS 2048 // T*B

// ---------------- scratch (device globals; no allocations allowed) ----------
__device__ float g_xgates[DT * DB * G4H];            // [t*B+b, 4H] fp32
__device__ float g_hgates[DB * G4H];                 // [b, 4H] fp32
__device__ __half g_hsh[NROWS * DH];                 // hs fp16 [t*B+b, H]
__device__ __half g_W2h[(size_t)DVP * H2];           // W2 fp16 (zero-padded rows)
__device__ __half g_W1t[DH * H2];                    // W1^T fp16 [H, 2H]
__device__ __half g_Wfh[(size_t)DVP * DH];           // Wf = W2@W1 fp16 [V, H]
__device__ float  g_b2f[DVP];                        // b2 + W2@b1
__device__ __half g_xseqh[NROWS * DE];               // gathered emb rows fp16
__device__ __half g_Wihh[G4H * DE];                  // W_ih fp16

// ---------------- helpers ----------------------------------------------------
__device__ __forceinline__ uint32_t smem_to_u32(const void* smem_ptr) {
    uint32_t addr;
    asm("{ .reg .u64 tmp; cvta.to.shared.u64 tmp, %1; cvt.u32.u64 %0, tmp; }"
        : "=r"(addr) : "l"(smem_ptr));
    return addr;
}

__device__ __forceinline__ void ldmx4(uint32_t* r, uint32_t addr) {
    asm volatile("ldmatrix.sync.aligned.m8n8.x4.shared.b16 {%0,%1,%2,%3}, [%4];"
                 : "=r"(r[0]), "=r"(r[1]), "=r"(r[2]), "=r"(r[3]) : "r"(addr));
}

__device__ __forceinline__ void mma16816(float* c, const uint32_t* a, const uint32_t* b) {
    asm volatile(
        "mma.sync.aligned.m16n8k16.row.col.f32.f16.f16.f32 "
        "{%0,%1,%2,%3}, {%4,%5,%6,%7}, {%8,%9}, {%0,%1,%2,%3};"
        : "+f"(c[0]), "+f"(c[1]), "+f"(c[2]), "+f"(c[3])
        : "r"(a[0]), "r"(a[1]), "r"(a[2]), "r"(a[3]), "r"(b[0]), "r"(b[1]));
}

__device__ __forceinline__ uint32_t pack2h(__half a, __half b) {
    return ((uint32_t)__half_as_ushort(b) << 16) | (uint32_t)__half_as_ushort(a);
}

__device__ __forceinline__ void cp_async16(uint32_t saddr, const void* gaddr) {
    asm volatile("cp.async.cg.shared.global [%0], [%1], 16;"
                 :: "r"(saddr), "l"(gaddr));
}

// XOR swizzle: conflict-free for cp.async stores and ldmatrix reads.
__device__ __forceinline__ uint32_t swz(int row, int chunk) {
    return (uint32_t)(row * 64 + ((chunk ^ ((row >> 1) & 3)) << 4));
}

__device__ __forceinline__ float fsig(float x) {
    return __fdividef(1.f, 1.f + __expf(-x));
}
__device__ __forceinline__ float ftanh(float x) {
    return __fdividef(2.f, 1.f + __expf(-2.f * x)) - 1.f;
}

// ---------------- SIMT tiled GEMM (h_gates only: M=32) ----------------------
#define SG_BM 64
#define SG_BN 64
#define SG_BK 16

__global__ __launch_bounds__(256) void sgemm_hgates(
    const float* __restrict__ A, const float* __restrict__ Bw,
    const float* __restrict__ bias, float* __restrict__ C,
    int M, int N, int K)
{
    __shared__ float As[SG_BK][SG_BM + 1];
    __shared__ float Bs[SG_BK][SG_BN + 1];
    const int n0 = blockIdx.x * SG_BN;
    const int tid = threadIdx.x;
    const int tx = tid & 15, ty = tid >> 4;
    const int arow = tid >> 2;
    const int aq = tid & 3;

    float acc[4][4];
#pragma unroll
    for (int i = 0; i < 4; i++)
#pragma unroll
        for (int j = 0; j < 4; j++) acc[i][j] = 0.f;

    int gm = arow; if (gm > M - 1) gm = M - 1;
    const float* aptr = A + (size_t)gm * K;
    const float* bptr = Bw + (size_t)(n0 + arow) * K;

    for (int k0 = 0; k0 < K; k0 += SG_BK) {
        float4 av = *(const float4*)(aptr + k0 + aq * 4);
        float4 bv = *(const float4*)(bptr + k0 + aq * 4);
        __syncthreads();
        As[aq * 4 + 0][arow] = av.x; As[aq * 4 + 1][arow] = av.y;
        As[aq * 4 + 2][arow] = av.z; As[aq * 4 + 3][arow] = av.w;
        Bs[aq * 4 + 0][arow] = bv.x; Bs[aq * 4 + 1][arow] = bv.y;
        Bs[aq * 4 + 2][arow] = bv.z; Bs[aq * 4 + 3][arow] = bv.w;
        __syncthreads();
#pragma unroll
        for (int k = 0; k < SG_BK; k++) {
            float a[4], b[4];
#pragma unroll
            for (int i = 0; i < 4; i++) a[i] = As[k][ty * 4 + i];
#pragma unroll
            for (int j = 0; j < 4; j++) b[j] = Bs[k][tx * 4 + j];
#pragma unroll
            for (int i = 0; i < 4; i++)
#pragma unroll
                for (int j = 0; j < 4; j++) acc[i][j] += a[i] * b[j];
        }
    }

#pragma unroll
    for (int i = 0; i < 4; i++) {
        int m = ty * 4 + i;
        if (m >= M) continue;
#pragma unroll
        for (int j = 0; j < 4; j++) {
            int n = n0 + tx * 4 + j;
            C[(size_t)m * N + n] = acc[i][j] + bias[n];
        }
    }
}

// ---------------- LSTM scan: depth-2 prefetch, fast-math, fp16 hs out --------
__global__ __launch_bounds__(128) void lstm_scan_kernel() {
    int idx = blockIdx.x * 128 + threadIdx.x;  // 0..16383
    int b = idx >> 9;
    int h = idx & (DH - 1);
    const float* hgp = g_hgates + b * G4H;
    float hgi = hgp[h], hgf = hgp[DH + h], hgg = hgp[2 * DH + h], hgo = hgp[3 * DH + h];

    const float* x = g_xgates + (size_t)b * G4H + h;
    const size_t tstride = (size_t)DB * G4H;
    __half* hsp = g_hsh + (size_t)b * DH + h;
    const size_t hstride = (size_t)DB * DH;

    float ai[2], af[2], ag[2], ao[2];
#pragma unroll
    for (int p = 0; p < 2; p++) {
        const float* xp = x + (size_t)p * tstride;
        ai[p] = xp[0]; af[p] = xp[DH]; ag[p] = xp[2 * DH]; ao[p] = xp[3 * DH];
    }
    float c = 0.f;
#pragma unroll 1
    for (int t = 0; t < DT; t++) {
        int p = t & 1;
        float gi = ai[p] + hgi;
        float gf = af[p] + hgf;
        float gg = ag[p] + hgg;
        float go = ao[p] + hgo;
        if (t + 2 < DT) {
            const float* xn = x + (size_t)(t + 2) * tstride;
            ai[p] = xn[0]; af[p] = xn[DH]; ag[p] = xn[2 * DH]; ao[p] = xn[3 * DH];
        }
        c = fsig(gf) * c + fsig(gi) * ftanh(gg);
        hsp[(size_t)t * hstride] = __float2half_rn(fsig(go) * ftanh(c));
    }
}

// ---------------- conversion / gather kernels ---------------------------------
// W2 fp32 -> fp16 (padded rows) AND b2f[row] = b2[row] + W2[row,:]·b1 (fused).
__global__ __launch_bounds__(256) void convert_w2_kernel(
    const float* __restrict__ W2, const float* __restrict__ b1,
    const float* __restrict__ b2)
{
    __shared__ float red[8];
    int row = blockIdx.x;                // 0..DVP-1
    int tid = threadIdx.x;
    int q = tid * 4;
    size_t o = (size_t)row * H2 + q;
    float4 v = make_float4(0.f, 0.f, 0.f, 0.f);
    if (row < DV) v = *(const float4*)(W2 + o);
    uint2 h = make_uint2(pack2h(__float2half_rn(v.x), __float2half_rn(v.y)),
                         pack2h(__float2half_rn(v.z), __float2half_rn(v.w)));
    *(uint2*)(g_W2h + o) = h;

    // fused b2f dot: sum_k W2[row,k]*b1[k]
    float4 bv = *(const float4*)(b1 + q);
    float s = v.x * bv.x + v.y * bv.y + v.z * bv.z + v.w * bv.w;
#pragma unroll
    for (int off = 16; off; off >>= 1) s += __shfl_xor_sync(0xffffffffu, s, off);
    if ((tid & 31) == 0) red[tid >> 5] = s;
    __syncthreads();
    if (tid == 0) {
        float t = 0.f;
#pragma unroll
        for (int w = 0; w < 8; w++) t += red[w];
        g_b2f[row] = (row < DV) ? (t + b2[row]) : 0.f;
    }
}

// W1 [2H, H] -> W1^T fp16 [H, 2H]
__global__ __launch_bounds__(256) void convert_w1t_kernel(const float* __restrict__ W1) {
    int h = blockIdx.x;                  // 0..DH-1
    int k0 = threadIdx.x * 4;            // 0..1023 step
    __half* dst = g_W1t + (size_t)h * H2 + k0;
#pragma unroll
    for (int j = 0; j < 4; j++)
        dst[j] = __float2half_rn(W1[(size_t)(k0 + j) * DH + h]);
}

// x_seq gather + fp16 convert: row m=t*B+b <- emb[tok(b, t?t-1:0)]
__global__ __launch_bounds__(64) void gather_xseq_kernel(
    const float* __restrict__ emb, const int* __restrict__ captions) {
    int m = blockIdx.x;
    int t = m >> 5, b = m & 31;
    int tt = t ? (t - 1) : 0;
    int tok = captions[b * DT + tt];
    const float* src = emb + (size_t)tok * DE;
    int q = threadIdx.x * 4;
    float4 v = *(const float4*)(src + q);
    uint2 h = make_uint2(pack2h(__float2half_rn(v.x), __float2half_rn(v.y)),
                         pack2h(__float2half_rn(v.z), __float2half_rn(v.w)));
    *(uint2*)(g_xseqh + (size_t)m * DE + q) = h;
}

__global__ __launch_bounds__(64) void convert_wih_kernel(const float* __restrict__ W_ih) {
    int row = blockIdx.x;                // 0..G4H-1
    int q = threadIdx.x * 4;
    size_t o = (size_t)row * DE + q;
    float4 v = *(const float4*)(W_ih + o);
    uint2 h = make_uint2(pack2h(__float2half_rn(v.x), __float2half_rn(v.y)),
                         pack2h(__float2half_rn(v.z), __float2half_rn(v.w)));
    *(uint2*)(g_Wihh + o) = h;
}

// ---------------- generic fp16 HMMA GEMM: C[m,n] = sum_k A[m,k]*B[n,k] -------
// OUT=0: fp32 row-major + bias. OUT=1: fp16 row-major, no bias.
// OUT=2: logits scatter out[(b*T+t)*V + v] = acc + bias[v], m = t*B+b.
// MAPSWAP: blockIdx.x -> n (use when n-blocks < m-blocks so consecutive CTAs
//          share the A tile and A streams DRAM once).
#define BM 128
#define BN 128
#define BK 32
#define ST_B   8192
#define STAGE_BYTES 16384
#define NSTAGE 4
#define SMEM_BIG (NSTAGE * STAGE_BYTES)

template <int OUT, bool MAPSWAP>
__global__ __launch_bounds__(256) void hgemm_kernel(
    const __half* __restrict__ A, const __half* __restrict__ Bm,
    const float* __restrict__ bias, void* __restrict__ outv,
    int K, int Ncols)
{
    extern __shared__ __align__(128) char smem[];
    const uint32_t sb0 = smem_to_u32(smem);
    const int tid = threadIdx.x;
    const int wid = tid >> 5, lane = tid & 31;
    const int m0 = (MAPSWAP ? blockIdx.y : blockIdx.x) * BM;
    const int n0 = (MAPSWAP ? blockIdx.x : blockIdx.y) * BN;
    const int wm = (wid & 1) * 64;
    const int wn = (wid >> 1) * 32;
    const int NT = K >> 5;

    float acc[4][4][4];
#pragma unroll
    for (int mi = 0; mi < 4; mi++)
#pragma unroll
        for (int ni = 0; ni < 4; ni++)
#pragma unroll
            for (int f = 0; f < 4; f++) acc[mi][ni][f] = 0.f;

    const int lrow = tid >> 2;         // 0..63
    const int lc = tid & 3;
    const __half* gA = A + (size_t)m0 * K;
    const __half* gB = Bm + (size_t)n0 * K;

    const int a_r = lane & 15;
    const int a_cb = lane >> 4;
    const int b_g = lane >> 3;
    const int b_r = (lane & 7) + ((b_g >> 1) * 8);
    const int b_cb = b_g & 1;

    auto issue_copies = [&](int s) {
        const uint32_t base = sb0 + (uint32_t)(s & (NSTAGE - 1)) * STAGE_BYTES;
        const int k0 = s * BK;
#pragma unroll
        for (int j = 0; j < 2; j++) {
            int row = lrow + j * 64;
            uint32_t so = swz(row, lc);
            size_t go = (size_t)row * K + k0 + lc * 8;
            cp_async16(base + so,        gA + go);
            cp_async16(base + ST_B + so, gB + go);
        }
    };

    // prologue: NSTAGE-1 stages in flight
#pragma unroll
    for (int s = 0; s < NSTAGE - 1; s++) {
        if (s < NT) issue_copies(s);
        asm volatile("cp.async.commit_group;");
    }

#pragma unroll 1
    for (int s = 0; s < NT; s++) {
        // keep the pipeline full; empty commit keeps group accounting uniform
        if (s + NSTAGE - 1 < NT) issue_copies(s + NSTAGE - 1);
        asm volatile("cp.async.commit_group;");
        asm volatile("cp.async.wait_group %0;" :: "n"(NSTAGE - 1));
        __syncthreads();

        const uint32_t base = sb0 + (uint32_t)(s & (NSTAGE - 1)) * STAGE_BYTES;
#pragma unroll
        for (int kk = 0; kk < BK; kk += 16) {
            const int cb = kk >> 3;
            uint32_t ah[4][4], bb[4][2];
#pragma unroll
            for (int mi = 0; mi < 4; mi++) {
                int row = wm + mi * 16 + a_r;
                ldmx4(ah[mi], base + swz(row, cb + a_cb));
            }
#pragma unroll
            for (int nb = 0; nb < 2; nb++) {
                int row = wn + nb * 16 + b_r;
                uint32_t t0[4];
                ldmx4(t0, base + ST_B + swz(row, cb + b_cb));
                bb[2 * nb][0] = t0[0]; bb[2 * nb][1] = t0[1];
                bb[2 * nb + 1][0] = t0[2]; bb[2 * nb + 1][1] = t0[3];
            }
#pragma unroll
            for (int mi = 0; mi < 4; mi++)
#pragma unroll
                for (int ni = 0; ni < 4; ni++)
                    mma16816(acc[mi][ni], ah[mi], bb[ni]);
        }
        __syncthreads();
    }

    // ---- epilogue ----
    const int gr = lane >> 2;
    const int gc = (lane & 3) * 2;
#pragma unroll
    for (int mi = 0; mi < 4; mi++) {
#pragma unroll
        for (int half = 0; half < 2; half++) {
            int m = m0 + wm + mi * 16 + gr + half * 8;
#pragma unroll
            for (int ni = 0; ni < 4; ni++) {
                int n = n0 + wn + ni * 8 + gc;
                float c0 = acc[mi][ni][half * 2 + 0];
                float c1 = acc[mi][ni][half * 2 + 1];
                if (OUT == 0) {
                    float2 o = make_float2(c0 + bias[n], c1 + bias[n + 1]);
                    *(float2*)((float*)outv + (size_t)m * Ncols + n) = o;
                } else if (OUT == 1) {
                    __half2 o = __floats2half2_rn(c0, c1);
                    *(__half2*)((__half*)outv + (size_t)m * Ncols + n) = o;
                } else {
                    int t = m >> 5, b = m & 31;
                    float* orow = (float*)outv + (size_t)(b * DT + t) * DV;
                    if (n < DV)     orow[n]     = c0 + bias[n];
                    if (n + 1 < DV) orow[n + 1] = c1 + bias[n + 1];
                }
            }
        }
    }
}

// ---------------- launch ----------------------------------------------------
extern "C" void kernel_launch(void* const* d_in, const int* in_sizes, int n_in,
                              void* d_out, int out_size) {
    const float* features = (const float*)d_in[0];
    const int*   captions = (const int*)d_in[1];
    const float* emb      = (const float*)d_in[2];
    const float* W_ih     = (const float*)d_in[3];
    const float* W_hh     = (const float*)d_in[4];
    const float* b_ih     = (const float*)d_in[5];
    const float* b_hh     = (const float*)d_in[6];
    const float* W1       = (const float*)d_in[7];
    const float* b1       = (const float*)d_in[8];
    const float* W2       = (const float*)d_in[9];
    const float* b2       = (const float*)d_in[10];
    float* out = (float*)d_out;

    float *xg_p, *hg_p;
    __half *w2h_p, *w1t_p, *wfh_p, *xsq_p, *wih_p, *hsh_p;
    float *b2f_p;
    cudaGetSymbolAddress((void**)&xg_p,  g_xgates);
    cudaGetSymbolAddress((void**)&hg_p,  g_hgates);
    cudaGetSymbolAddress((void**)&w2h_p, g_W2h);
    cudaGetSymbolAddress((void**)&w1t_p, g_W1t);
    cudaGetSymbolAddress((void**)&wfh_p, g_Wfh);
    cudaGetSymbolAddress((void**)&xsq_p, g_xseqh);
    cudaGetSymbolAddress((void**)&wih_p, g_Wihh);
    cudaGetSymbolAddress((void**)&hsh_p, g_hsh);
    cudaGetSymbolAddress((void**)&b2f_p, g_b2f);

    cudaFuncSetAttribute(hgemm_kernel<0, false>, cudaFuncAttributeMaxDynamicSharedMemorySize, SMEM_BIG);
    cudaFuncSetAttribute(hgemm_kernel<1, true>,  cudaFuncAttributeMaxDynamicSharedMemorySize, SMEM_BIG);
    cudaFuncSetAttribute(hgemm_kernel<2, false>, cudaFuncAttributeMaxDynamicSharedMemorySize, SMEM_BIG);

    // weight preprocessing (b2f fused into convert_w2)
    convert_w2_kernel<<<DVP, 256>>>(W2, b1, b2);
    convert_w1t_kernel<<<DH, 256>>>(W1);
    // fold: Wf[v,h] = sum_k W2[v,k] * W1[k,h]  (M=DVP, N=DH, K=2H)
    // MAPSWAP grid(4, 393): consecutive CTAs share the A (W2h) tile -> A streams once.
    hgemm_kernel<1, true><<<dim3(DH / BN, DVP / BM), 256, SMEM_BIG>>>(
        w2h_p, w1t_p, nullptr, wfh_p, H2, DH);

    // x path
    gather_xseq_kernel<<<NROWS, 64>>>(emb, captions);
    convert_wih_kernel<<<G4H, 64>>>(W_ih);
    // x_gates = x_seq @ W_ih^T + b_ih  (M=2048, N=2048, K=256)
    hgemm_kernel<0, false><<<dim3(NROWS / BM, G4H / BN), 256, SMEM_BIG>>>(
        xsq_p, wih_p, b_ih, xg_p, DE, G4H);

    // h_gates = features @ W_hh^T + b_hh  (32x2048, K=512)
    sgemm_hgates<<<dim3(G4H / SG_BN, 1), 256>>>(
        features, W_hh, b_hh, hg_p, DB, G4H, DH);

    // LSTM scan (writes hs fp16)
    lstm_scan_kernel<<<DB * DH / 128, 128>>>();

    // logits = hs @ Wf^T + b2f  (M=2048, N=DVP, K=512)
    hgemm_kernel<2, false><<<dim3(NROWS / BM, DVP / BN), 256, SMEM_BIG>>>(
        hsh_p, wfh_p, b2f_p, out, DH, 0);
}